// round 13
// baseline (speedup 1.0000x reference)
#include <cuda_runtime.h>
#include <cuda_bf16.h>

#define NT 128
#define TOK 64

// g_b1: w_qkv row-image (R10-proven): head-grouped rows n' = h*48+blk*16+ii
//       (-> col blk*128+h*16+ii), 256B rows, XOR-16B swizzle. Head h = 12KB slice.
// g_f2: w_proj GEMM2 B fragments (R12-proven): [hd][jp][lane] x 16B.
__device__ __align__(16) unsigned char g_b1h[98304];
__device__ __align__(16) unsigned char g_b1l[98304];
__device__ __align__(16) unsigned char g_f2h[32768];
__device__ __align__(16) unsigned char g_f2l[32768];

#define SWZ(r, b) ((unsigned)((r) * 256 + ((b) ^ (((r) & 7) << 4))))

// smem map (bytes) — 59392 total => 3 CTAs/SM (smem); regs capped 170 via launch_bounds
#define OF_BQ  0u        // 1536
#define OF_BP  1536u     // 512
#define OF_AH  2048u     // 16384: x image hi (64 rows x 256B)
#define OF_AL  18432u    // 16384: x image lo
#define OF_B1H 34816u    // 12288: current head B1 hi (48 rows)
#define OF_B1L 47104u    // 12288
#define SMEM_TOTAL 59392

__device__ __forceinline__ unsigned smem_u32(const void* p) {
    unsigned a;
    asm("{ .reg .u64 t; cvta.to.shared.u64 t, %1; cvt.u32.u64 %0, t; }" : "=r"(a) : "l"(p));
    return a;
}
__device__ __forceinline__ unsigned pk2(float a, float b) {
    __nv_bfloat162 t = __floats2bfloat162_rn(a, b);
    return *reinterpret_cast<unsigned*>(&t);
}
__device__ __forceinline__ float bfr(float v) {
    return __bfloat162float(__float2bfloat16_rn(v));
}
__device__ __forceinline__ void ldsm4(unsigned* r, unsigned addr) {
    asm volatile("ldmatrix.sync.aligned.m8n8.x4.shared.b16 {%0,%1,%2,%3}, [%4];"
                 : "=r"(r[0]), "=r"(r[1]), "=r"(r[2]), "=r"(r[3]) : "r"(addr));
}
__device__ __forceinline__ void mma16816(float* d, const unsigned* a, const unsigned* b) {
    asm volatile(
        "mma.sync.aligned.m16n8k16.row.col.f32.bf16.bf16.f32 "
        "{%0,%1,%2,%3}, {%4,%5,%6,%7}, {%8,%9}, {%0,%1,%2,%3};"
        : "+f"(d[0]), "+f"(d[1]), "+f"(d[2]), "+f"(d[3])
        : "r"(a[0]), "r"(a[1]), "r"(a[2]), "r"(a[3]), "r"(b[0]), "r"(b[1]));
}
__device__ __forceinline__ void cp16(unsigned dst, const void* src) {
    asm volatile("cp.async.cg.shared.global [%0], [%1], 16;" :: "r"(dst), "l"(src));
}
__device__ __forceinline__ float ex2f(float x) {
    float r; asm("ex2.approx.f32 %0, %1;" : "=f"(r) : "f"(x)); return r;
}
__device__ __forceinline__ float rcpf(float x) {
    float r; asm("rcp.approx.f32 %0, %1;" : "=f"(r) : "f"(x)); return r;
}

// ---------------- prep: fp32 weights -> images ----------------
__global__ void prep_weights(const float* __restrict__ wq, const float* __restrict__ wp) {
    int i = blockIdx.x * blockDim.x + threadIdx.x;
    if (i < 6144) {                        // w_qkv row-image (R10 branch, verbatim)
        int n = i >> 4, kc = i & 15, k0 = kc * 8;
        int h = n / 48, rem = n % 48, blk = rem >> 4, ii = rem & 15;
        int col = blk * 128 + h * 16 + ii;
        float hf[8], lf[8];
        #pragma unroll
        for (int j = 0; j < 8; j++) {
            float v = wq[(k0 + j) * 384 + col];
            hf[j] = bfr(v);
            lf[j] = v - hf[j];
        }
        unsigned off = SWZ(n, kc * 16);
        *(uint4*)(g_b1h + off) = make_uint4(pk2(hf[0], hf[1]), pk2(hf[2], hf[3]),
                                            pk2(hf[4], hf[5]), pk2(hf[6], hf[7]));
        *(uint4*)(g_b1l + off) = make_uint4(pk2(lf[0], lf[1]), pk2(lf[2], lf[3]),
                                            pk2(lf[4], lf[5]), pk2(lf[6], lf[7]));
    } else if (i < 8192) {                 // w_proj fragment arrays (R12 branch, verbatim)
        int i2 = i - 6144;
        int lane = i2 & 31, jp = (i2 >> 5) & 7, hd = i2 >> 8;
        int k0 = hd * 16, kp = 2 * (lane & 3);
        int n0 = 2 * jp * 8 + (lane >> 2), n1 = n0 + 8;
        float vals[8];
        vals[0] = wp[(k0 + kp) * 128 + n0];     vals[1] = wp[(k0 + kp + 1) * 128 + n0];
        vals[2] = wp[(k0 + kp + 8) * 128 + n0]; vals[3] = wp[(k0 + kp + 9) * 128 + n0];
        vals[4] = wp[(k0 + kp) * 128 + n1];     vals[5] = wp[(k0 + kp + 1) * 128 + n1];
        vals[6] = wp[(k0 + kp + 8) * 128 + n1]; vals[7] = wp[(k0 + kp + 9) * 128 + n1];
        float hf[8], lf[8];
        #pragma unroll
        for (int j = 0; j < 8; j++) { hf[j] = bfr(vals[j]); lf[j] = vals[j] - hf[j]; }
        *(uint4*)(g_f2h + i2 * 16) = make_uint4(pk2(hf[0], hf[1]), pk2(hf[2], hf[3]),
                                                pk2(hf[4], hf[5]), pk2(hf[6], hf[7]));
        *(uint4*)(g_f2l + i2 * 16) = make_uint4(pk2(lf[0], lf[1]), pk2(lf[2], lf[3]),
                                                pk2(lf[4], lf[5]), pk2(lf[6], lf[7]));
    }
}

// ---------------- main kernel: 4 warps, per-head rounds, 3 CTAs/SM ----------------
__global__ void __launch_bounds__(NT, 3)
chan_attn_h8(const float* __restrict__ x, const float* __restrict__ bq,
             const float* __restrict__ bp, float* __restrict__ out)
{
    extern __shared__ __align__(16) unsigned char smem[];
    const unsigned sb = smem_u32(smem);
    const int tid = threadIdx.x, wid = tid >> 5, lane = tid & 31;
    const int p = lane & 3;
    const long long tb = (long long)blockIdx.x * TOK;

    float* sBq = (float*)(smem + OF_BQ);
    float* sBp = (float*)(smem + OF_BP);
    for (int i = tid; i < 384; i += NT) sBq[i] = bq[i];
    if (tid < 128) sBp[tid] = bp[tid];

    // prologue: B1 head 0 via cp.async (12288 B each of hi/lo => 6 iters @ NT=128)
    #pragma unroll
    for (int it = 0; it < 6; it++) {
        int i = tid + it * NT;
        cp16(sb + OF_B1H + i * 16, g_b1h + i * 16);
        cp16(sb + OF_B1L + i * 16, g_b1l + i * 16);
    }
    asm volatile("cp.async.commit_group;" ::: "memory");

    // build A image from x (64 rows x 32 float4 = 2048 => 16 iters)
    {
        const float4* x4 = (const float4*)(x + tb * 128);
        #pragma unroll
        for (int it = 0; it < 16; it++) {
            int i = tid + it * NT;
            int m = i >> 5, c4 = i & 31;
            float4 v = x4[i];
            float h0 = bfr(v.x), h1 = bfr(v.y), h2 = bfr(v.z), h3 = bfr(v.w);
            unsigned off = SWZ(m, c4 * 8);
            *(uint2*)(smem + OF_AH + off) = make_uint2(pk2(h0, h1), pk2(h2, h3));
            *(uint2*)(smem + OF_AL + off) =
                make_uint2(pk2(v.x - h0, v.y - h1), pk2(v.z - h2, v.w - h3));
        }
    }

    const int a_r = (lane & 7) + ((lane >> 3) & 1) * 8;
    const int a_bs = (lane >> 4) * 16;
    const int b_r = (lane & 7) + (lane >> 4) * 8;
    const int b_bs = ((lane >> 3) & 1) * 16;

    const uint4* f2h = (const uint4*)g_f2h;
    const uint4* f2l = (const uint4*)g_f2l;

    float d2[16][4] = {};   // GEMM2 accumulator: m16 x n128, persistent

    #pragma unroll 1
    for (int hh = 0; hh < 8; hh++) {
        asm volatile("cp.async.wait_group 0;" ::: "memory");
        __syncthreads();   // B1(head hh) resident; (hh==0: A image too)

        // ---- GEMM1: d1 = A[m16 rows wid*16..] @ B1[head hh]  (m16 x n48, K=128) ----
        float d1[6][4] = {};
        #pragma unroll
        for (int kc = 0; kc < 8; kc++) {
            const int kb = kc * 32;
            unsigned ah[4], al[4], bh[3][4], bl[3][4];
            {
                unsigned off = SWZ(wid * 16 + a_r, kb + a_bs);
                ldsm4(ah, sb + OF_AH + off);
                ldsm4(al, sb + OF_AL + off);
            }
            #pragma unroll
            for (int g = 0; g < 3; g++) {
                unsigned off = SWZ(g * 16 + b_r, kb + b_bs);   // local rows 0..47
                ldsm4(bh[g], sb + OF_B1H + off);
                ldsm4(bl[g], sb + OF_B1L + off);
            }
            #pragma unroll
            for (int j = 0; j < 6; j++) {
                const unsigned* BH = bh[j >> 1] + (j & 1) * 2;
                const unsigned* BL = bl[j >> 1] + (j & 1) * 2;
                mma16816(d1[j], ah, BH);
                mma16816(d1[j], ah, BL);
                mma16816(d1[j], al, BH);
            }
        }
        __syncthreads();   // all warps done reading B1(hh)

        // refill B1 for next head (drains under softmax/GEMM2)
        if (hh < 7) {
            const unsigned char* s1 = g_b1h + (hh + 1) * 12288;
            const unsigned char* s2 = g_b1l + (hh + 1) * 12288;
            #pragma unroll
            for (int it = 0; it < 6; it++) {
                int i = tid + it * NT;
                cp16(sb + OF_B1H + i * 16, s1 + i * 16);
                cp16(sb + OF_B1L + i * 16, s2 + i * 16);
            }
            asm volatile("cp.async.commit_group;" ::: "memory");
        }

        // ---- in-register softmax for head hh; output = GEMM2 A-fragments ----
        unsigned a2h[4], a2l[4];
        {
            const float scl2 = 0.0883883476483184405f * 1.4426950408889634f;
            const int c0 = 2 * p, c2 = 8 + 2 * p;
            float qb0 = sBq[hh * 16 + c0], qb1 = sBq[hh * 16 + c0 + 1];
            float qb2 = sBq[hh * 16 + c2], qb3 = sBq[hh * 16 + c2 + 1];
            float kb0 = sBq[128 + hh * 16 + c0], kb1 = sBq[128 + hh * 16 + c0 + 1];
            float kb2 = sBq[128 + hh * 16 + c2], kb3 = sBq[128 + hh * 16 + c2 + 1];
            float vb0 = sBq[256 + hh * 16 + c0], vb1 = sBq[256 + hh * 16 + c0 + 1];
            float vb2 = sBq[256 + hh * 16 + c2], vb3 = sBq[256 + hh * 16 + c2 + 1];

            float o[2][4];
            #pragma unroll
            for (int rh = 0; rh < 2; rh++) {
                float kk0 = d1[2][rh * 2 + 0] + kb0;
                float kk1 = d1[2][rh * 2 + 1] + kb1;
                float kk2 = d1[3][rh * 2 + 0] + kb2;
                float kk3 = d1[3][rh * 2 + 1] + kb3;
                float vv0 = d1[4][rh * 2 + 0] + vb0;
                float vv1 = d1[4][rh * 2 + 1] + vb1;
                float vv2 = d1[5][rh * 2 + 0] + vb2;
                float vv3 = d1[5][rh * 2 + 1] + vb3;
                float kf[16], vf[16];
                #pragma unroll
                for (int pp = 0; pp < 4; pp++) {
                    int sl = (lane & ~3) | pp;
                    kf[2 * pp]         = __shfl_sync(0xffffffffu, kk0, sl);
                    kf[2 * pp + 1]     = __shfl_sync(0xffffffffu, kk1, sl);
                    kf[8 + 2 * pp]     = __shfl_sync(0xffffffffu, kk2, sl);
                    kf[8 + 2 * pp + 1] = __shfl_sync(0xffffffffu, kk3, sl);
                    vf[2 * pp]         = __shfl_sync(0xffffffffu, vv0, sl);
                    vf[2 * pp + 1]     = __shfl_sync(0xffffffffu, vv1, sl);
                    vf[8 + 2 * pp]     = __shfl_sync(0xffffffffu, vv2, sl);
                    vf[8 + 2 * pp + 1] = __shfl_sync(0xffffffffu, vv3, sl);
                }
                float qv[4] = {qb0, qb1, qb2, qb3};
                #pragma unroll
                for (int i = 0; i < 4; i++) {
                    float ci = (d1[i >> 1][rh * 2 + (i & 1)] + qv[i]) * scl2;
                    float s = 0.f, a = 0.f;
                    #pragma unroll
                    for (int j = 0; j < 16; j++) {
                        float e = ex2f(ci * kf[j]);
                        s += e;
                        a = fmaf(e, vf[j], a);
                    }
                    o[rh][i] = a * rcpf(s);
                }
            }
            float h00 = bfr(o[0][0]), h01 = bfr(o[0][1]);
            float h10 = bfr(o[1][0]), h11 = bfr(o[1][1]);
            float h02 = bfr(o[0][2]), h03 = bfr(o[0][3]);
            float h12 = bfr(o[1][2]), h13 = bfr(o[1][3]);
            a2h[0] = pk2(h00, h01);  a2h[1] = pk2(h10, h11);
            a2h[2] = pk2(h02, h03);  a2h[3] = pk2(h12, h13);
            a2l[0] = pk2(o[0][0] - h00, o[0][1] - h01);
            a2l[1] = pk2(o[1][0] - h10, o[1][1] - h11);
            a2l[2] = pk2(o[0][2] - h02, o[0][3] - h03);
            a2l[3] = pk2(o[1][2] - h12, o[1][3] - h13);
        }

        // ---- GEMM2: d2 += A2(head hh) @ Wproj[k-block hh]  (m16 x n128, frag LDG) ----
        #pragma unroll
        for (int jp = 0; jp < 8; jp++) {
            const int base2 = (hh * 8 + jp) * 32 + lane;
            uint4 VH = f2h[base2];
            uint4 VL = f2l[base2];
            const unsigned* vhp = (const unsigned*)&VH;
            const unsigned* vlp = (const unsigned*)&VL;
            #pragma unroll
            for (int half = 0; half < 2; half++) {
                int j = 2 * jp + half;
                mma16816(d2[j], a2h, vhp + half * 2);
                mma16816(d2[j], a2h, vlp + half * 2);
                mma16816(d2[j], a2l, vhp + half * 2);
            }
        }
    }

    // ---- epilogue: d2 + bias -> gmem ----
    {
        float* og = out + tb * 128;
        const int rl = wid * 16 + (lane >> 2);
        const int cb = p * 2;
        #pragma unroll
        for (int j = 0; j < 16; j++) {
            int col = cb + j * 8;
            float b0 = sBp[col], b1 = sBp[col + 1];
            *(float2*)(og + rl * 128 + col) =
                make_float2(d2[j][0] + b0, d2[j][1] + b1);
            *(float2*)(og + (rl + 8) * 128 + col) =
                make_float2(d2[j][2] + b0, d2[j][3] + b1);
        }
    }
}

extern "C" void kernel_launch(void* const* d_in, const int* in_sizes, int n_in,
                              void* d_out, int out_size)
{
    const float *x = nullptr, *wq = nullptr, *bq = nullptr, *wp = nullptr, *bp = nullptr;
    long long xsz = 0;
    for (int i = 0; i < n_in; i++) {
        switch (in_sizes[i]) {
            case 49152: wq = (const float*)d_in[i]; break;
            case 384:   bq = (const float*)d_in[i]; break;
            case 16384: wp = (const float*)d_in[i]; break;
            case 128:   bp = (const float*)d_in[i]; break;
            default:    x  = (const float*)d_in[i]; xsz = in_sizes[i]; break;
        }
    }
    const int tokens = (int)(xsz / 128);

    prep_weights<<<32, 256>>>(wq, wp);

    cudaFuncSetAttribute(chan_attn_h8,
                         cudaFuncAttributeMaxDynamicSharedMemorySize, SMEM_TOTAL);
    chan_attn_h8<<<tokens / TOK, NT, SMEM_TOTAL>>>(x, bq, bp, (float*)d_out);
}

// round 14
// speedup vs baseline: 1.2046x; 1.2046x over previous
#include <cuda_runtime.h>
#include <cuda_bf16.h>
#include <cuda_fp16.h>

#define NT 256
#define TOK 64

// g_b1: w_qkv SINGLE-fp16 row-image: head-grouped rows n' = h*48+blk*16+ii
//       (-> col blk*128+h*16+ii), 256B rows, XOR-16B swizzle. Head slice=12KB... 2 heads/round=24KB.
// g_b2: w_proj bf16 hi/lo, per-ROUND slice layout (R10-proven):
//       offset = r*8192 + s*4096 + n*32 + ((c ^ ((n>>2)&1))<<4), head = 2r+s.
__device__ __align__(16) unsigned char g_b1h[98304];
__device__ __align__(16) unsigned char g_b2h[32768];
__device__ __align__(16) unsigned char g_b2l[32768];

#define SWZ(r, b) ((unsigned)((r) * 256 + ((b) ^ (((r) & 7) << 4))))

// smem map (bytes) — 83968 total => 2 CTAs/SM
#define OF_BQ    0u        // 1536
#define OF_BP    1536u     // 512
#define OF_SCR   2048u     // 8192: A2-frag exchange [wid8][slot8][lane32]
#define OF_AH    10240u    // 16384: x image hi fp16 (64 rows x 256B)
#define OF_AL    26624u    // 16384: x image lo fp16
#define OF_B1    43008u    // 24576: current round B1 fp16 (2 heads, 96 rows)
#define OF_B2RH  67584u    // 8192: current round B2 slice hi (2 slots x 4KB)
#define OF_B2RL  75776u    // 8192
#define SMEM_TOTAL 83968

__device__ __forceinline__ unsigned smem_u32(const void* p) {
    unsigned a;
    asm("{ .reg .u64 t; cvta.to.shared.u64 t, %1; cvt.u32.u64 %0, t; }" : "=r"(a) : "l"(p));
    return a;
}
__device__ __forceinline__ unsigned pk2(float a, float b) {      // bf16x2
    __nv_bfloat162 t = __floats2bfloat162_rn(a, b);
    return *reinterpret_cast<unsigned*>(&t);
}
__device__ __forceinline__ unsigned pk2h(float a, float b) {     // fp16x2
    __half2 t = __floats2half2_rn(a, b);
    return *reinterpret_cast<unsigned*>(&t);
}
__device__ __forceinline__ float bfr(float v) {
    return __bfloat162float(__float2bfloat16_rn(v));
}
__device__ __forceinline__ float hfr(float v) {
    return __half2float(__float2half_rn(v));
}
__device__ __forceinline__ void ldsm4(unsigned* r, unsigned addr) {
    asm volatile("ldmatrix.sync.aligned.m8n8.x4.shared.b16 {%0,%1,%2,%3}, [%4];"
                 : "=r"(r[0]), "=r"(r[1]), "=r"(r[2]), "=r"(r[3]) : "r"(addr));
}
__device__ __forceinline__ void mma_bf(float* d, const unsigned* a, const unsigned* b) {
    asm volatile(
        "mma.sync.aligned.m16n8k16.row.col.f32.bf16.bf16.f32 "
        "{%0,%1,%2,%3}, {%4,%5,%6,%7}, {%8,%9}, {%0,%1,%2,%3};"
        : "+f"(d[0]), "+f"(d[1]), "+f"(d[2]), "+f"(d[3])
        : "r"(a[0]), "r"(a[1]), "r"(a[2]), "r"(a[3]), "r"(b[0]), "r"(b[1]));
}
__device__ __forceinline__ void mma_fp(float* d, const unsigned* a, const unsigned* b) {
    asm volatile(
        "mma.sync.aligned.m16n8k16.row.col.f32.f16.f16.f32 "
        "{%0,%1,%2,%3}, {%4,%5,%6,%7}, {%8,%9}, {%0,%1,%2,%3};"
        : "+f"(d[0]), "+f"(d[1]), "+f"(d[2]), "+f"(d[3])
        : "r"(a[0]), "r"(a[1]), "r"(a[2]), "r"(a[3]), "r"(b[0]), "r"(b[1]));
}
__device__ __forceinline__ void cp16(unsigned dst, const void* src) {
    asm volatile("cp.async.cg.shared.global [%0], [%1], 16;" :: "r"(dst), "l"(src));
}
__device__ __forceinline__ float ex2f(float x) {
    float r; asm("ex2.approx.f32 %0, %1;" : "=f"(r) : "f"(x)); return r;
}
__device__ __forceinline__ float rcpf(float x) {
    float r; asm("rcp.approx.f32 %0, %1;" : "=f"(r) : "f"(x)); return r;
}

// ---------------- prep: fp32 weights -> images ----------------
__global__ void prep_weights(const float* __restrict__ wq, const float* __restrict__ wp) {
    int i = blockIdx.x * blockDim.x + threadIdx.x;
    if (i < 6144) {                        // w_qkv: single fp16 row-image
        int n = i >> 4, kc = i & 15, k0 = kc * 8;
        int h = n / 48, rem = n % 48, blk = rem >> 4, ii = rem & 15;
        int col = blk * 128 + h * 16 + ii;
        float v[8];
        #pragma unroll
        for (int j = 0; j < 8; j++) v[j] = wq[(k0 + j) * 384 + col];
        unsigned off = SWZ(n, kc * 16);
        *(uint4*)(g_b1h + off) = make_uint4(pk2h(v[0], v[1]), pk2h(v[2], v[3]),
                                            pk2h(v[4], v[5]), pk2h(v[6], v[7]));
    } else if (i < 8192) {                 // w_proj bf16 hi/lo per-round slices (R10 verbatim)
        int j2 = i - 6144;
        int n = j2 >> 4, kc = j2 & 15, k0 = kc * 8;
        int hd = kc >> 1, c = kc & 1, r = hd >> 1, s = hd & 1;
        float hf[8], lf[8];
        #pragma unroll
        for (int j = 0; j < 8; j++) {
            float v = wp[(k0 + j) * 128 + n];
            hf[j] = bfr(v);
            lf[j] = v - hf[j];
        }
        unsigned off = (unsigned)(r * 8192 + s * 4096 + n * 32 +
                                  ((c ^ ((n >> 2) & 1)) << 4));
        *(uint4*)(g_b2h + off) = make_uint4(pk2(hf[0], hf[1]), pk2(hf[2], hf[3]),
                                            pk2(hf[4], hf[5]), pk2(hf[6], hf[7]));
        *(uint4*)(g_b2l + off) = make_uint4(pk2(lf[0], lf[1]), pk2(lf[2], lf[3]),
                                            pk2(lf[4], lf[5]), pk2(lf[6], lf[7]));
    }
}

// ---------------- main fused kernel: 8 warps, m16, fp16 GEMM1, 2 CTAs/SM ----------------
__global__ void __launch_bounds__(NT, 2)
chan_attn_fp16(const float* __restrict__ x, const float* __restrict__ bq,
               const float* __restrict__ bp, float* __restrict__ out)
{
    extern __shared__ __align__(16) unsigned char smem[];
    const unsigned sb = smem_u32(smem);
    const int tid = threadIdx.x, wid = tid >> 5, lane = tid & 31;
    const int wm = wid >> 1, wh = wid & 1, p = lane & 3;
    const long long tb = (long long)blockIdx.x * TOK;

    float* sBq = (float*)(smem + OF_BQ);
    float* sBp = (float*)(smem + OF_BP);
    for (int i = tid; i < 384; i += NT) sBq[i] = bq[i];
    if (tid < 128) sBp[tid] = bp[tid];

    // prologue cp.async: B1 round0 (24576B => 6 iters) + B2 slice round0 (2 iters each)
    #pragma unroll
    for (int it = 0; it < 6; it++) {
        int i = tid + it * NT;
        cp16(sb + OF_B1 + i * 16, g_b1h + i * 16);
    }
    #pragma unroll
    for (int it = 0; it < 2; it++) {
        int i = tid + it * NT;
        cp16(sb + OF_B2RH + i * 16, g_b2h + i * 16);
        cp16(sb + OF_B2RL + i * 16, g_b2l + i * 16);
    }
    asm volatile("cp.async.commit_group;" ::: "memory");

    // build A image from x (fp16 hi/lo, swizzled [m][k])
    {
        const float4* x4 = (const float4*)(x + tb * 128);
        #pragma unroll
        for (int it = 0; it < 8; it++) {
            int i = tid + it * NT;
            int m = i >> 5, c4 = i & 31;
            float4 v = x4[i];
            float h0 = hfr(v.x), h1 = hfr(v.y), h2 = hfr(v.z), h3 = hfr(v.w);
            unsigned off = SWZ(m, c4 * 8);
            *(uint2*)(smem + OF_AH + off) = make_uint2(pk2h(h0, h1), pk2h(h2, h3));
            *(uint2*)(smem + OF_AL + off) =
                make_uint2(pk2h(v.x - h0, v.y - h1), pk2h(v.z - h2, v.w - h3));
        }
    }

    const int a_r = (lane & 7) + ((lane >> 3) & 1) * 8;
    const int a_bs = (lane >> 4) * 16;
    const int b_r = (lane & 7) + (lane >> 4) * 8;
    const int b_bs = ((lane >> 3) & 1) * 16;
    const int b2c = (lane >> 3) & 1;

    float d2[8][4] = {};   // GEMM2 accumulator: m16 x n64

    unsigned* scr = (unsigned*)(smem + OF_SCR);
    const int sbase = wid * 256 + lane;
    const int pbase = (wid ^ 1) * 256 + lane;

    #pragma unroll 1
    for (int r = 0; r < 4; r++) {
        asm volatile("cp.async.wait_group 0;" ::: "memory");
        __syncthreads();   // B1(r), B2 slice(r), (r==0: A image) resident

        // ---- GEMM1 (fp16 2-term): d1 = (Ah+Al)[m16] @ B1[head 2r+wh]  (m16 x n48) ----
        float d1[6][4] = {};
        #pragma unroll
        for (int kc = 0; kc < 8; kc++) {
            const int kb = kc * 32;
            unsigned ah[4], al[4], bh[3][4];
            {
                unsigned off = SWZ(wm * 16 + a_r, kb + a_bs);
                ldsm4(ah, sb + OF_AH + off);
                ldsm4(al, sb + OF_AL + off);
            }
            #pragma unroll
            for (int g = 0; g < 3; g++) {
                unsigned off = SWZ(wh * 48 + g * 16 + b_r, kb + b_bs);
                ldsm4(bh[g], sb + OF_B1 + off);
            }
            #pragma unroll
            for (int j = 0; j < 6; j++) {
                const unsigned* BH = bh[j >> 1] + (j & 1) * 2;
                mma_fp(d1[j], ah, BH);
                mma_fp(d1[j], al, BH);
            }
        }
        __syncthreads();   // all warps done reading B1

        // refill B1 for next round (drains under softmax/GEMM2)
        if (r < 3) {
            const unsigned char* s1 = g_b1h + (r + 1) * 24576;
            #pragma unroll
            for (int it = 0; it < 6; it++) {
                int i = tid + it * NT;
                cp16(sb + OF_B1 + i * 16, s1 + i * 16);
            }
            asm volatile("cp.async.commit_group;" ::: "memory");
        }

        // ---- in-register softmax for head hh ----
        const int hh = 2 * r + wh;
        unsigned a2h[4], a2l[4];
        {
            const float scl2 = 0.0883883476483184405f * 1.4426950408889634f;
            const int c0 = 2 * p, c2 = 8 + 2 * p;
            float qb0 = sBq[hh * 16 + c0], qb1 = sBq[hh * 16 + c0 + 1];
            float qb2 = sBq[hh * 16 + c2], qb3 = sBq[hh * 16 + c2 + 1];
            float kb0 = sBq[128 + hh * 16 + c0], kb1 = sBq[128 + hh * 16 + c0 + 1];
            float kb2 = sBq[128 + hh * 16 + c2], kb3 = sBq[128 + hh * 16 + c2 + 1];
            float vb0 = sBq[256 + hh * 16 + c0], vb1 = sBq[256 + hh * 16 + c0 + 1];
            float vb2 = sBq[256 + hh * 16 + c2], vb3 = sBq[256 + hh * 16 + c2 + 1];

            float o[2][4];
            #pragma unroll
            for (int rh = 0; rh < 2; rh++) {
                float kk0 = d1[2][rh * 2 + 0] + kb0;
                float kk1 = d1[2][rh * 2 + 1] + kb1;
                float kk2 = d1[3][rh * 2 + 0] + kb2;
                float kk3 = d1[3][rh * 2 + 1] + kb3;
                float vv0 = d1[4][rh * 2 + 0] + vb0;
                float vv1 = d1[4][rh * 2 + 1] + vb1;
                float vv2 = d1[5][rh * 2 + 0] + vb2;
                float vv3 = d1[5][rh * 2 + 1] + vb3;
                float kf[16], vf[16];
                #pragma unroll
                for (int pp = 0; pp < 4; pp++) {
                    int sl = (lane & ~3) | pp;
                    kf[2 * pp]         = __shfl_sync(0xffffffffu, kk0, sl);
                    kf[2 * pp + 1]     = __shfl_sync(0xffffffffu, kk1, sl);
                    kf[8 + 2 * pp]     = __shfl_sync(0xffffffffu, kk2, sl);
                    kf[8 + 2 * pp + 1] = __shfl_sync(0xffffffffu, kk3, sl);
                    vf[2 * pp]         = __shfl_sync(0xffffffffu, vv0, sl);
                    vf[2 * pp + 1]     = __shfl_sync(0xffffffffu, vv1, sl);
                    vf[8 + 2 * pp]     = __shfl_sync(0xffffffffu, vv2, sl);
                    vf[8 + 2 * pp + 1] = __shfl_sync(0xffffffffu, vv3, sl);
                }
                float qv[4] = {qb0, qb1, qb2, qb3};
                #pragma unroll
                for (int i = 0; i < 4; i++) {
                    float ci = (d1[i >> 1][rh * 2 + (i & 1)] + qv[i]) * scl2;
                    float s = 0.f, a = 0.f;
                    #pragma unroll
                    for (int j = 0; j < 16; j++) {
                        float e = ex2f(ci * kf[j]);
                        s += e;
                        a = fmaf(e, vf[j], a);
                    }
                    o[rh][i] = a * rcpf(s);
                }
            }
            float h00 = bfr(o[0][0]), h01 = bfr(o[0][1]);
            float h10 = bfr(o[1][0]), h11 = bfr(o[1][1]);
            float h02 = bfr(o[0][2]), h03 = bfr(o[0][3]);
            float h12 = bfr(o[1][2]), h13 = bfr(o[1][3]);
            a2h[0] = pk2(h00, h01);  a2h[1] = pk2(h10, h11);
            a2h[2] = pk2(h02, h03);  a2h[3] = pk2(h12, h13);
            a2l[0] = pk2(o[0][0] - h00, o[0][1] - h01);
            a2l[1] = pk2(o[1][0] - h10, o[1][1] - h11);
            a2l[2] = pk2(o[0][2] - h02, o[0][3] - h03);
            a2l[3] = pk2(o[1][2] - h12, o[1][3] - h13);
        }

        // ---- exchange A2 fragments with pair warp (other head of round) ----
        #pragma unroll
        for (int e = 0; e < 4; e++) {
            scr[sbase + e * 32] = a2h[e];
            scr[sbase + (4 + e) * 32] = a2l[e];
        }
        asm volatile("bar.sync %0, %1;" :: "r"(1 + wm), "r"(64) : "memory");
        unsigned p2h[4], p2l[4];
        #pragma unroll
        for (int e = 0; e < 4; e++) {
            p2h[e] = scr[pbase + e * 32];
            p2l[e] = scr[pbase + (4 + e) * 32];
        }

        // ---- GEMM2 (bf16 3-term): both heads of this round ----
        #pragma unroll
        for (int which = 0; which < 2; which++) {
            const unsigned* AH = which ? p2h : a2h;
            const unsigned* AL = which ? p2l : a2l;
            const int s = which ? (wh ^ 1) : wh;
            unsigned b2h_[4][4], b2l_[4][4];
            #pragma unroll
            for (int g = 0; g < 4; g++) {
                int row = wh * 64 + g * 16 + b_r;
                unsigned off = (unsigned)(s * 4096 + row * 32 +
                                          ((b2c ^ ((row >> 2) & 1)) << 4));
                ldsm4(b2h_[g], sb + OF_B2RH + off);
                ldsm4(b2l_[g], sb + OF_B2RL + off);
            }
            #pragma unroll
            for (int j = 0; j < 8; j++) {
                const unsigned* BH = b2h_[j >> 1] + (j & 1) * 2;
                const unsigned* BL = b2l_[j >> 1] + (j & 1) * 2;
                mma_bf(d2[j], AH, BH);
                mma_bf(d2[j], AH, BL);
                mma_bf(d2[j], AL, BH);
            }
        }
        __syncthreads();   // GEMM2 B2-slice + scratch reads done

        // refill B2 slice for next round (drains under next GEMM1)
        if (r < 3) {
            const unsigned char* s1 = g_b2h + (r + 1) * 8192;
            const unsigned char* s2 = g_b2l + (r + 1) * 8192;
            #pragma unroll
            for (int it = 0; it < 2; it++) {
                int i = tid + it * NT;
                cp16(sb + OF_B2RH + i * 16, s1 + i * 16);
                cp16(sb + OF_B2RL + i * 16, s2 + i * 16);
            }
            asm volatile("cp.async.commit_group;" ::: "memory");
        }
    }

    // ---- epilogue: d2 + bias -> gmem ----
    {
        float* og = out + tb * 128;
        const int rl = wm * 16 + (lane >> 2);
        const int cb = wh * 64 + p * 2;
        #pragma unroll
        for (int j = 0; j < 8; j++) {
            int col = cb + j * 8;
            float b0 = sBp[col], b1 = sBp[col + 1];
            *(float2*)(og + rl * 128 + col) =
                make_float2(d2[j][0] + b0, d2[j][1] + b1);
            *(float2*)(og + (rl + 8) * 128 + col) =
                make_float2(d2[j][2] + b0, d2[j][3] + b1);
        }
    }
}

extern "C" void kernel_launch(void* const* d_in, const int* in_sizes, int n_in,
                              void* d_out, int out_size)
{
    const float *x = nullptr, *wq = nullptr, *bq = nullptr, *wp = nullptr, *bp = nullptr;
    long long xsz = 0;
    for (int i = 0; i < n_in; i++) {
        switch (in_sizes[i]) {
            case 49152: wq = (const float*)d_in[i]; break;
            case 384:   bq = (const float*)d_in[i]; break;
            case 16384: wp = (const float*)d_in[i]; break;
            case 128:   bp = (const float*)d_in[i]; break;
            default:    x  = (const float*)d_in[i]; xsz = in_sizes[i]; break;
        }
    }
    const int tokens = (int)(xsz / 128);

    prep_weights<<<32, 256>>>(wq, wp);

    cudaFuncSetAttribute(chan_attn_fp16,
                         cudaFuncAttributeMaxDynamicSharedMemorySize, SMEM_TOTAL);
    chan_attn_fp16<<<tokens / TOK, NT, SMEM_TOTAL>>>(x, bq, bp, (float*)d_out);
}

// round 15
// speedup vs baseline: 1.4033x; 1.1649x over previous
#include <cuda_runtime.h>
#include <cuda_bf16.h>
#include <cuda_fp16.h>

#define NT 256
#define TOK 64

// g_b1: w_qkv SINGLE-fp16 row-image: head-grouped rows n' = h*48+blk*16+ii
//       (-> col blk*128+h*16+ii), 256B rows, XOR-16B swizzle. 2 heads/round = 24KB.
// g_b2: w_proj SINGLE-fp16, per-ROUND slice layout:
//       offset = r*8192 + s*4096 + n*32 + ((c ^ ((n>>2)&1))<<4), head = 2r+s,
//       chunk c covers k = hd*16 + c*8 .. +7.
__device__ __align__(16) unsigned char g_b1h[98304];
__device__ __align__(16) unsigned char g_b2h[32768];

#define SWZ(r, b) ((unsigned)((r) * 256 + ((b) ^ (((r) & 7) << 4))))

// smem map (bytes) — 59392 total => 2 CTAs/SM with big headroom
#define OF_BQ   0u        // 1536
#define OF_BP   1536u     // 512
#define OF_SCR  2048u     // 8192: A2-frag exchange [wid8][slot8][lane32]
#define OF_AH   10240u    // 16384: x image single fp16 (64 rows x 256B)
#define OF_B1   26624u    // 24576: current round B1 fp16 (2 heads, 96 rows)
#define OF_B2R  51200u    // 8192: current round B2 fp16 slice (2 slots x 4KB)
#define SMEM_TOTAL 59392

__device__ __forceinline__ unsigned smem_u32(const void* p) {
    unsigned a;
    asm("{ .reg .u64 t; cvta.to.shared.u64 t, %1; cvt.u32.u64 %0, t; }" : "=r"(a) : "l"(p));
    return a;
}
__device__ __forceinline__ unsigned pk2h(float a, float b) {     // fp16x2
    __half2 t = __floats2half2_rn(a, b);
    return *reinterpret_cast<unsigned*>(&t);
}
__device__ __forceinline__ float hfr(float v) {
    return __half2float(__float2half_rn(v));
}
__device__ __forceinline__ void ldsm4(unsigned* r, unsigned addr) {
    asm volatile("ldmatrix.sync.aligned.m8n8.x4.shared.b16 {%0,%1,%2,%3}, [%4];"
                 : "=r"(r[0]), "=r"(r[1]), "=r"(r[2]), "=r"(r[3]) : "r"(addr));
}
__device__ __forceinline__ void mma_fp(float* d, const unsigned* a, const unsigned* b) {
    asm volatile(
        "mma.sync.aligned.m16n8k16.row.col.f32.f16.f16.f32 "
        "{%0,%1,%2,%3}, {%4,%5,%6,%7}, {%8,%9}, {%0,%1,%2,%3};"
        : "+f"(d[0]), "+f"(d[1]), "+f"(d[2]), "+f"(d[3])
        : "r"(a[0]), "r"(a[1]), "r"(a[2]), "r"(a[3]), "r"(b[0]), "r"(b[1]));
}
__device__ __forceinline__ void cp16(unsigned dst, const void* src) {
    asm volatile("cp.async.cg.shared.global [%0], [%1], 16;" :: "r"(dst), "l"(src));
}
__device__ __forceinline__ float ex2f(float x) {
    float r; asm("ex2.approx.f32 %0, %1;" : "=f"(r) : "f"(x)); return r;
}
__device__ __forceinline__ float rcpf(float x) {
    float r; asm("rcp.approx.f32 %0, %1;" : "=f"(r) : "f"(x)); return r;
}

// ---------------- prep: fp32 weights -> fp16 images ----------------
__global__ void prep_weights(const float* __restrict__ wq, const float* __restrict__ wp) {
    int i = blockIdx.x * blockDim.x + threadIdx.x;
    if (i < 6144) {                        // w_qkv: single fp16 row-image
        int n = i >> 4, kc = i & 15, k0 = kc * 8;
        int h = n / 48, rem = n % 48, blk = rem >> 4, ii = rem & 15;
        int col = blk * 128 + h * 16 + ii;
        float v[8];
        #pragma unroll
        for (int j = 0; j < 8; j++) v[j] = wq[(k0 + j) * 384 + col];
        unsigned off = SWZ(n, kc * 16);
        *(uint4*)(g_b1h + off) = make_uint4(pk2h(v[0], v[1]), pk2h(v[2], v[3]),
                                            pk2h(v[4], v[5]), pk2h(v[6], v[7]));
    } else if (i < 8192) {                 // w_proj: single fp16 per-round slices
        int j2 = i - 6144;
        int n = j2 >> 4, kc = j2 & 15, k0 = kc * 8;
        int hd = kc >> 1, c = kc & 1, r = hd >> 1, s = hd & 1;
        float v[8];
        #pragma unroll
        for (int j = 0; j < 8; j++) v[j] = wp[(k0 + j) * 128 + n];
        unsigned off = (unsigned)(r * 8192 + s * 4096 + n * 32 +
                                  ((c ^ ((n >> 2) & 1)) << 4));
        *(uint4*)(g_b2h + off) = make_uint4(pk2h(v[0], v[1]), pk2h(v[2], v[3]),
                                            pk2h(v[4], v[5]), pk2h(v[6], v[7]));
    }
}

// ---------------- main fused kernel: all-fp16 operands, 8 warps, 2 CTAs/SM ----------------
__global__ void __launch_bounds__(NT, 2)
chan_attn_fp16(const float* __restrict__ x, const float* __restrict__ bq,
               const float* __restrict__ bp, float* __restrict__ out)
{
    extern __shared__ __align__(16) unsigned char smem[];
    const unsigned sb = smem_u32(smem);
    const int tid = threadIdx.x, wid = tid >> 5, lane = tid & 31;
    const int wm = wid >> 1, wh = wid & 1, p = lane & 3;
    const long long tb = (long long)blockIdx.x * TOK;

    float* sBq = (float*)(smem + OF_BQ);
    float* sBp = (float*)(smem + OF_BP);
    for (int i = tid; i < 384; i += NT) sBq[i] = bq[i];
    if (tid < 128) sBp[tid] = bp[tid];

    // prologue cp.async: B1 round0 (24576B => 6 iters) + B2 slice round0 (8192B => 2 iters)
    #pragma unroll
    for (int it = 0; it < 6; it++) {
        int i = tid + it * NT;
        cp16(sb + OF_B1 + i * 16, g_b1h + i * 16);
    }
    #pragma unroll
    for (int it = 0; it < 2; it++) {
        int i = tid + it * NT;
        cp16(sb + OF_B2R + i * 16, g_b2h + i * 16);
    }
    asm volatile("cp.async.commit_group;" ::: "memory");

    // build A image from x (single fp16, swizzled [m][k])
    {
        const float4* x4 = (const float4*)(x + tb * 128);
        #pragma unroll
        for (int it = 0; it < 8; it++) {
            int i = tid + it * NT;
            int m = i >> 5, c4 = i & 31;
            float4 v = x4[i];
            unsigned off = SWZ(m, c4 * 8);
            *(uint2*)(smem + OF_AH + off) = make_uint2(pk2h(v.x, v.y), pk2h(v.z, v.w));
        }
    }

    const int a_r = (lane & 7) + ((lane >> 3) & 1) * 8;
    const int a_bs = (lane >> 4) * 16;
    const int b_r = (lane & 7) + (lane >> 4) * 8;
    const int b_bs = ((lane >> 3) & 1) * 16;
    const int b2c = (lane >> 3) & 1;

    float d2[8][4] = {};   // GEMM2 accumulator: m16 x n64

    unsigned* scr = (unsigned*)(smem + OF_SCR);
    const int sbase = wid * 256 + lane;
    const int pbase = (wid ^ 1) * 256 + lane;

    #pragma unroll 1
    for (int r = 0; r < 4; r++) {
        asm volatile("cp.async.wait_group 0;" ::: "memory");
        __syncthreads();   // B1(r), B2 slice(r), (r==0: A image) resident

        // ---- GEMM1 (fp16 1-term): d1 = A[m16] @ B1[head 2r+wh]  (m16 x n48, K=128) ----
        float d1[6][4] = {};
        #pragma unroll
        for (int kc = 0; kc < 8; kc++) {
            const int kb = kc * 32;
            unsigned ah[4], bh[3][4];
            {
                unsigned off = SWZ(wm * 16 + a_r, kb + a_bs);
                ldsm4(ah, sb + OF_AH + off);
            }
            #pragma unroll
            for (int g = 0; g < 3; g++) {
                unsigned off = SWZ(wh * 48 + g * 16 + b_r, kb + b_bs);
                ldsm4(bh[g], sb + OF_B1 + off);
            }
            #pragma unroll
            for (int j = 0; j < 6; j++) {
                const unsigned* BH = bh[j >> 1] + (j & 1) * 2;
                mma_fp(d1[j], ah, BH);
            }
        }
        __syncthreads();   // all warps done reading B1

        // refill B1 for next round (drains under softmax/GEMM2)
        if (r < 3) {
            const unsigned char* s1 = g_b1h + (r + 1) * 24576;
            #pragma unroll
            for (int it = 0; it < 6; it++) {
                int i = tid + it * NT;
                cp16(sb + OF_B1 + i * 16, s1 + i * 16);
            }
            asm volatile("cp.async.commit_group;" ::: "memory");
        }

        // ---- in-register softmax for head hh ----
        const int hh = 2 * r + wh;
        unsigned a2h[4], a2l[4];
        {
            const float scl2 = 0.0883883476483184405f * 1.4426950408889634f;
            const int c0 = 2 * p, c2 = 8 + 2 * p;
            float qb0 = sBq[hh * 16 + c0], qb1 = sBq[hh * 16 + c0 + 1];
            float qb2 = sBq[hh * 16 + c2], qb3 = sBq[hh * 16 + c2 + 1];
            float kb0 = sBq[128 + hh * 16 + c0], kb1 = sBq[128 + hh * 16 + c0 + 1];
            float kb2 = sBq[128 + hh * 16 + c2], kb3 = sBq[128 + hh * 16 + c2 + 1];
            float vb0 = sBq[256 + hh * 16 + c0], vb1 = sBq[256 + hh * 16 + c0 + 1];
            float vb2 = sBq[256 + hh * 16 + c2], vb3 = sBq[256 + hh * 16 + c2 + 1];

            float o[2][4];
            #pragma unroll
            for (int rh = 0; rh < 2; rh++) {
                float kk0 = d1[2][rh * 2 + 0] + kb0;
                float kk1 = d1[2][rh * 2 + 1] + kb1;
                float kk2 = d1[3][rh * 2 + 0] + kb2;
                float kk3 = d1[3][rh * 2 + 1] + kb3;
                float vv0 = d1[4][rh * 2 + 0] + vb0;
                float vv1 = d1[4][rh * 2 + 1] + vb1;
                float vv2 = d1[5][rh * 2 + 0] + vb2;
                float vv3 = d1[5][rh * 2 + 1] + vb3;
                float kf[16], vf[16];
                #pragma unroll
                for (int pp = 0; pp < 4; pp++) {
                    int sl = (lane & ~3) | pp;
                    kf[2 * pp]         = __shfl_sync(0xffffffffu, kk0, sl);
                    kf[2 * pp + 1]     = __shfl_sync(0xffffffffu, kk1, sl);
                    kf[8 + 2 * pp]     = __shfl_sync(0xffffffffu, kk2, sl);
                    kf[8 + 2 * pp + 1] = __shfl_sync(0xffffffffu, kk3, sl);
                    vf[2 * pp]         = __shfl_sync(0xffffffffu, vv0, sl);
                    vf[2 * pp + 1]     = __shfl_sync(0xffffffffu, vv1, sl);
                    vf[8 + 2 * pp]     = __shfl_sync(0xffffffffu, vv2, sl);
                    vf[8 + 2 * pp + 1] = __shfl_sync(0xffffffffu, vv3, sl);
                }
                float qv[4] = {qb0, qb1, qb2, qb3};
                #pragma unroll
                for (int i = 0; i < 4; i++) {
                    float ci = (d1[i >> 1][rh * 2 + (i & 1)] + qv[i]) * scl2;
                    float s = 0.f, a = 0.f;
                    #pragma unroll
                    for (int j = 0; j < 16; j++) {
                        float e = ex2f(ci * kf[j]);
                        s += e;
                        a = fmaf(e, vf[j], a);
                    }
                    o[rh][i] = a * rcpf(s);
                }
            }
            // pack A2 fragments as fp16 hi/lo (exact split; consumed by fp16 GEMM2)
            float h00 = hfr(o[0][0]), h01 = hfr(o[0][1]);
            float h10 = hfr(o[1][0]), h11 = hfr(o[1][1]);
            float h02 = hfr(o[0][2]), h03 = hfr(o[0][3]);
            float h12 = hfr(o[1][2]), h13 = hfr(o[1][3]);
            a2h[0] = pk2h(h00, h01);  a2h[1] = pk2h(h10, h11);
            a2h[2] = pk2h(h02, h03);  a2h[3] = pk2h(h12, h13);
            a2l[0] = pk2h(o[0][0] - h00, o[0][1] - h01);
            a2l[1] = pk2h(o[1][0] - h10, o[1][1] - h11);
            a2l[2] = pk2h(o[0][2] - h02, o[0][3] - h03);
            a2l[3] = pk2h(o[1][2] - h12, o[1][3] - h13);
        }

        // ---- exchange A2 fragments with pair warp (other head of round) ----
        #pragma unroll
        for (int e = 0; e < 4; e++) {
            scr[sbase + e * 32] = a2h[e];
            scr[sbase + (4 + e) * 32] = a2l[e];
        }
        asm volatile("bar.sync %0, %1;" :: "r"(1 + wm), "r"(64) : "memory");
        unsigned p2h[4], p2l[4];
        #pragma unroll
        for (int e = 0; e < 4; e++) {
            p2h[e] = scr[pbase + e * 32];
            p2l[e] = scr[pbase + (4 + e) * 32];
        }

        // ---- GEMM2 (fp16 2-term): both heads of this round ----
        #pragma unroll
        for (int which = 0; which < 2; which++) {
            const unsigned* AH = which ? p2h : a2h;
            const unsigned* AL = which ? p2l : a2l;
            const int s = which ? (wh ^ 1) : wh;
            unsigned b2_[4][4];
            #pragma unroll
            for (int g = 0; g < 4; g++) {
                int row = wh * 64 + g * 16 + b_r;
                unsigned off = (unsigned)(s * 4096 + row * 32 +
                                          ((b2c ^ ((row >> 2) & 1)) << 4));
                ldsm4(b2_[g], sb + OF_B2R + off);
            }
            #pragma unroll
            for (int j = 0; j < 8; j++) {
                const unsigned* BB = b2_[j >> 1] + (j & 1) * 2;
                mma_fp(d2[j], AH, BB);
                mma_fp(d2[j], AL, BB);
            }
        }
        __syncthreads();   // GEMM2 B2-slice + scratch reads done

        // refill B2 slice for next round (drains under next GEMM1)
        if (r < 3) {
            const unsigned char* s1 = g_b2h + (r + 1) * 8192;
            #pragma unroll
            for (int it = 0; it < 2; it++) {
                int i = tid + it * NT;
                cp16(sb + OF_B2R + i * 16, s1 + i * 16);
            }
            asm volatile("cp.async.commit_group;" ::: "memory");
        }
    }

    // ---- epilogue: d2 + bias -> gmem ----
    {
        float* og = out + tb * 128;
        const int rl = wm * 16 + (lane >> 2);
        const int cb = wh * 64 + p * 2;
        #pragma unroll
        for (int j = 0; j < 8; j++) {
            int col = cb + j * 8;
            float b0 = sBp[col], b1 = sBp[col + 1];
            *(float2*)(og + rl * 128 + col) =
                make_float2(d2[j][0] + b0, d2[j][1] + b1);
            *(float2*)(og + (rl + 8) * 128 + col) =
                make_float2(d2[j][2] + b0, d2[j][3] + b1);
        }
    }
}

extern "C" void kernel_launch(void* const* d_in, const int* in_sizes, int n_in,
                              void* d_out, int out_size)
{
    const float *x = nullptr, *wq = nullptr, *bq = nullptr, *wp = nullptr, *bp = nullptr;
    long long xsz = 0;
    for (int i = 0; i < n_in; i++) {
        switch (in_sizes[i]) {
            case 49152: wq = (const float*)d_in[i]; break;
            case 384:   bq = (const float*)d_in[i]; break;
            case 16384: wp = (const float*)d_in[i]; break;
            case 128:   bp = (const float*)d_in[i]; break;
            default:    x  = (const float*)d_in[i]; xsz = in_sizes[i]; break;
        }
    }
    const int tokens = (int)(xsz / 128);

    prep_weights<<<32, 256>>>(wq, wp);

    cudaFuncSetAttribute(chan_attn_fp16,
                         cudaFuncAttributeMaxDynamicSharedMemorySize, SMEM_TOTAL);
    chan_attn_fp16<<<tokens / TOK, NT, SMEM_TOTAL>>>(x, bq, bp, (float*)d_out);
}

// round 16
// speedup vs baseline: 1.6069x; 1.1451x over previous
#include <cuda_runtime.h>
#include <cuda_bf16.h>
#include <cuda_fp16.h>

#define NT 256
#define TOK 64

// g_b1: w_qkv SINGLE-fp16 row-image: head-grouped rows n' = h*48+blk*16+ii
//       (-> col blk*128+h*16+ii), 256B rows, XOR-16B swizzle. 2 heads/round = 24KB.
// g_b2: w_proj SINGLE-fp16, per-ROUND slice layout:
//       offset = r*8192 + s*4096 + n*32 + ((c ^ ((n>>2)&1))<<4), head = 2r+s.
__device__ __align__(16) unsigned char g_b1h[98304];
__device__ __align__(16) unsigned char g_b2h[32768];

#define SWZ(r, b) ((unsigned)((r) * 256 + ((b) ^ (((r) & 7) << 4))))

// smem map (bytes) — 59392 total => 2 CTAs/SM
#define OF_BQ   0u        // 1536
#define OF_BP   1536u     // 512
#define OF_SCR  2048u     // 8192: A2-frag exchange [wid8][slot8][lane32]
#define OF_AH   10240u    // 16384: x image single fp16 (64 rows x 256B)
#define OF_B1   26624u    // 24576: current round B1 fp16 (2 heads, 96 rows)
#define OF_B2R  51200u    // 8192: current round B2 fp16 slice (2 slots x 4KB)
#define SMEM_TOTAL 59392

__device__ __forceinline__ unsigned smem_u32(const void* p) {
    unsigned a;
    asm("{ .reg .u64 t; cvta.to.shared.u64 t, %1; cvt.u32.u64 %0, t; }" : "=r"(a) : "l"(p));
    return a;
}
__device__ __forceinline__ unsigned pk2h(float a, float b) {     // fp16x2
    __half2 t = __floats2half2_rn(a, b);
    return *reinterpret_cast<unsigned*>(&t);
}
__device__ __forceinline__ float hfr(float v) {
    return __half2float(__float2half_rn(v));
}
__device__ __forceinline__ void ldsm4(unsigned* r, unsigned addr) {
    asm volatile("ldmatrix.sync.aligned.m8n8.x4.shared.b16 {%0,%1,%2,%3}, [%4];"
                 : "=r"(r[0]), "=r"(r[1]), "=r"(r[2]), "=r"(r[3]) : "r"(addr));
}
__device__ __forceinline__ void mma_fp(float* d, const unsigned* a, const unsigned* b) {
    asm volatile(
        "mma.sync.aligned.m16n8k16.row.col.f32.f16.f16.f32 "
        "{%0,%1,%2,%3}, {%4,%5,%6,%7}, {%8,%9}, {%0,%1,%2,%3};"
        : "+f"(d[0]), "+f"(d[1]), "+f"(d[2]), "+f"(d[3])
        : "r"(a[0]), "r"(a[1]), "r"(a[2]), "r"(a[3]), "r"(b[0]), "r"(b[1]));
}
__device__ __forceinline__ void cp16(unsigned dst, const void* src) {
    asm volatile("cp.async.cg.shared.global [%0], [%1], 16;" :: "r"(dst), "l"(src));
}
__device__ __forceinline__ unsigned hmul2u(unsigned a, unsigned b) {
    unsigned d;
    asm("mul.rn.f16x2 %0, %1, %2;" : "=r"(d) : "r"(a), "r"(b));
    return d;
}
__device__ __forceinline__ unsigned ex2h2(unsigned x) {          // 2 exps / 1 MUFU
    unsigned r;
    asm("ex2.approx.f16x2 %0, %1;" : "=r"(r) : "r"(x));
    return r;
}
__device__ __forceinline__ float rcpf(float x) {
    float r; asm("rcp.approx.f32 %0, %1;" : "=f"(r) : "f"(x)); return r;
}

// ---------------- prep: fp32 weights -> fp16 images ----------------
__global__ void prep_weights(const float* __restrict__ wq, const float* __restrict__ wp) {
    int i = blockIdx.x * blockDim.x + threadIdx.x;
    if (i < 6144) {                        // w_qkv: single fp16 row-image
        int n = i >> 4, kc = i & 15, k0 = kc * 8;
        int h = n / 48, rem = n % 48, blk = rem >> 4, ii = rem & 15;
        int col = blk * 128 + h * 16 + ii;
        float v[8];
        #pragma unroll
        for (int j = 0; j < 8; j++) v[j] = wq[(k0 + j) * 384 + col];
        unsigned off = SWZ(n, kc * 16);
        *(uint4*)(g_b1h + off) = make_uint4(pk2h(v[0], v[1]), pk2h(v[2], v[3]),
                                            pk2h(v[4], v[5]), pk2h(v[6], v[7]));
    } else if (i < 8192) {                 // w_proj: single fp16 per-round slices
        int j2 = i - 6144;
        int n = j2 >> 4, kc = j2 & 15, k0 = kc * 8;
        int hd = kc >> 1, c = kc & 1, r = hd >> 1, s = hd & 1;
        float v[8];
        #pragma unroll
        for (int j = 0; j < 8; j++) v[j] = wp[(k0 + j) * 128 + n];
        unsigned off = (unsigned)(r * 8192 + s * 4096 + n * 32 +
                                  ((c ^ ((n >> 2) & 1)) << 4));
        *(uint4*)(g_b2h + off) = make_uint4(pk2h(v[0], v[1]), pk2h(v[2], v[3]),
                                            pk2h(v[4], v[5]), pk2h(v[6], v[7]));
    }
}

// ---------------- main fused kernel: fp16 operands + f16x2 exp softmax ----------------
__global__ void __launch_bounds__(NT, 2)
chan_attn_fp16(const float* __restrict__ x, const float* __restrict__ bq,
               const float* __restrict__ bp, float* __restrict__ out)
{
    extern __shared__ __align__(16) unsigned char smem[];
    const unsigned sb = smem_u32(smem);
    const int tid = threadIdx.x, wid = tid >> 5, lane = tid & 31;
    const int wm = wid >> 1, wh = wid & 1, p = lane & 3;
    const long long tb = (long long)blockIdx.x * TOK;

    float* sBq = (float*)(smem + OF_BQ);
    float* sBp = (float*)(smem + OF_BP);
    for (int i = tid; i < 384; i += NT) sBq[i] = bq[i];
    if (tid < 128) sBp[tid] = bp[tid];

    // prologue cp.async: B1 round0 (6 iters) + B2 slice round0 (2 iters)
    #pragma unroll
    for (int it = 0; it < 6; it++) {
        int i = tid + it * NT;
        cp16(sb + OF_B1 + i * 16, g_b1h + i * 16);
    }
    #pragma unroll
    for (int it = 0; it < 2; it++) {
        int i = tid + it * NT;
        cp16(sb + OF_B2R + i * 16, g_b2h + i * 16);
    }
    asm volatile("cp.async.commit_group;" ::: "memory");

    // build A image from x (single fp16, swizzled [m][k])
    {
        const float4* x4 = (const float4*)(x + tb * 128);
        #pragma unroll
        for (int it = 0; it < 8; it++) {
            int i = tid + it * NT;
            int m = i >> 5, c4 = i & 31;
            float4 v = x4[i];
            unsigned off = SWZ(m, c4 * 8);
            *(uint2*)(smem + OF_AH + off) = make_uint2(pk2h(v.x, v.y), pk2h(v.z, v.w));
        }
    }

    const int a_r = (lane & 7) + ((lane >> 3) & 1) * 8;
    const int a_bs = (lane >> 4) * 16;
    const int b_r = (lane & 7) + (lane >> 4) * 8;
    const int b_bs = ((lane >> 3) & 1) * 16;
    const int b2c = (lane >> 3) & 1;

    float d2[8][4] = {};   // GEMM2 accumulator: m16 x n64

    unsigned* scr = (unsigned*)(smem + OF_SCR);
    const int sbase = wid * 256 + lane;
    const int pbase = (wid ^ 1) * 256 + lane;

    #pragma unroll 1
    for (int r = 0; r < 4; r++) {
        asm volatile("cp.async.wait_group 0;" ::: "memory");
        __syncthreads();   // B1(r), B2 slice(r), (r==0: A image) resident

        // ---- GEMM1 (fp16 1-term): d1 = A[m16] @ B1[head 2r+wh]  (m16 x n48) ----
        float d1[6][4] = {};
        #pragma unroll
        for (int kc = 0; kc < 8; kc++) {
            const int kb = kc * 32;
            unsigned ah[4], bh[3][4];
            {
                unsigned off = SWZ(wm * 16 + a_r, kb + a_bs);
                ldsm4(ah, sb + OF_AH + off);
            }
            #pragma unroll
            for (int g = 0; g < 3; g++) {
                unsigned off = SWZ(wh * 48 + g * 16 + b_r, kb + b_bs);
                ldsm4(bh[g], sb + OF_B1 + off);
            }
            #pragma unroll
            for (int j = 0; j < 6; j++) {
                const unsigned* BH = bh[j >> 1] + (j & 1) * 2;
                mma_fp(d1[j], ah, BH);
            }
        }
        __syncthreads();   // all warps done reading B1

        // refill B1 for next round
        if (r < 3) {
            const unsigned char* s1 = g_b1h + (r + 1) * 24576;
            #pragma unroll
            for (int it = 0; it < 6; it++) {
                int i = tid + it * NT;
                cp16(sb + OF_B1 + i * 16, s1 + i * 16);
            }
            asm volatile("cp.async.commit_group;" ::: "memory");
        }

        // ---- in-register softmax for head hh (f16x2 exp, fp32 accumulation) ----
        const int hh = 2 * r + wh;
        unsigned a2h[4], a2l[4];
        {
            const float scl2 = 0.0883883476483184405f * 1.4426950408889634f;
            const int c0 = 2 * p, c2 = 8 + 2 * p;
            float qb0 = sBq[hh * 16 + c0], qb1 = sBq[hh * 16 + c0 + 1];
            float qb2 = sBq[hh * 16 + c2], qb3 = sBq[hh * 16 + c2 + 1];
            float kb0 = sBq[128 + hh * 16 + c0], kb1 = sBq[128 + hh * 16 + c0 + 1];
            float kb2 = sBq[128 + hh * 16 + c2], kb3 = sBq[128 + hh * 16 + c2 + 1];
            float vb0 = sBq[256 + hh * 16 + c0], vb1 = sBq[256 + hh * 16 + c0 + 1];
            float vb2 = sBq[256 + hh * 16 + c2], vb3 = sBq[256 + hh * 16 + c2 + 1];

            float o[2][4];
            #pragma unroll
            for (int rh = 0; rh < 2; rh++) {
                float kk0 = d1[2][rh * 2 + 0] + kb0;
                float kk1 = d1[2][rh * 2 + 1] + kb1;
                float kk2 = d1[3][rh * 2 + 0] + kb2;
                float kk3 = d1[3][rh * 2 + 1] + kb3;
                float vv0 = d1[4][rh * 2 + 0] + vb0;
                float vv1 = d1[4][rh * 2 + 1] + vb1;
                float vv2 = d1[5][rh * 2 + 0] + vb2;
                float vv3 = d1[5][rh * 2 + 1] + vb3;
                float kf[16], vf[16];
                #pragma unroll
                for (int pp = 0; pp < 4; pp++) {
                    int sl = (lane & ~3) | pp;
                    kf[2 * pp]         = __shfl_sync(0xffffffffu, kk0, sl);
                    kf[2 * pp + 1]     = __shfl_sync(0xffffffffu, kk1, sl);
                    kf[8 + 2 * pp]     = __shfl_sync(0xffffffffu, kk2, sl);
                    kf[8 + 2 * pp + 1] = __shfl_sync(0xffffffffu, kk3, sl);
                    vf[2 * pp]         = __shfl_sync(0xffffffffu, vv0, sl);
                    vf[2 * pp + 1]     = __shfl_sync(0xffffffffu, vv1, sl);
                    vf[8 + 2 * pp]     = __shfl_sync(0xffffffffu, vv2, sl);
                    vf[8 + 2 * pp + 1] = __shfl_sync(0xffffffffu, vv3, sl);
                }
                // pack k into fp16x2 pairs (once per rh, reused over 4 i)
                unsigned kh[8];
                #pragma unroll
                for (int jp = 0; jp < 8; jp++)
                    kh[jp] = pk2h(kf[2 * jp], kf[2 * jp + 1]);

                float qv[4] = {qb0, qb1, qb2, qb3};
                #pragma unroll
                for (int i = 0; i < 4; i++) {
                    float ci = (d1[i >> 1][rh * 2 + (i & 1)] + qv[i]) * scl2;
                    unsigned ch = pk2h(ci, ci);
                    float s = 0.f, a = 0.f;
                    #pragma unroll
                    for (int jp = 0; jp < 8; jp++) {
                        unsigned e2 = ex2h2(hmul2u(ch, kh[jp]));
                        __half2 eh = *reinterpret_cast<__half2*>(&e2);
                        float e0 = __low2float(eh), e1 = __high2float(eh);
                        s += e0 + e1;
                        a = fmaf(e0, vf[2 * jp], a);
                        a = fmaf(e1, vf[2 * jp + 1], a);
                    }
                    o[rh][i] = a * rcpf(s);
                }
            }
            // pack A2 fragments as fp16 hi/lo (exact split; consumed by fp16 GEMM2)
            float h00 = hfr(o[0][0]), h01 = hfr(o[0][1]);
            float h10 = hfr(o[1][0]), h11 = hfr(o[1][1]);
            float h02 = hfr(o[0][2]), h03 = hfr(o[0][3]);
            float h12 = hfr(o[1][2]), h13 = hfr(o[1][3]);
            a2h[0] = pk2h(h00, h01);  a2h[1] = pk2h(h10, h11);
            a2h[2] = pk2h(h02, h03);  a2h[3] = pk2h(h12, h13);
            a2l[0] = pk2h(o[0][0] - h00, o[0][1] - h01);
            a2l[1] = pk2h(o[1][0] - h10, o[1][1] - h11);
            a2l[2] = pk2h(o[0][2] - h02, o[0][3] - h03);
            a2l[3] = pk2h(o[1][2] - h12, o[1][3] - h13);
        }

        // ---- exchange A2 fragments with pair warp (other head of round) ----
        #pragma unroll
        for (int e = 0; e < 4; e++) {
            scr[sbase + e * 32] = a2h[e];
            scr[sbase + (4 + e) * 32] = a2l[e];
        }
        asm volatile("bar.sync %0, %1;" :: "r"(1 + wm), "r"(64) : "memory");
        unsigned p2h[4], p2l[4];
        #pragma unroll
        for (int e = 0; e < 4; e++) {
            p2h[e] = scr[pbase + e * 32];
            p2l[e] = scr[pbase + (4 + e) * 32];
        }

        // ---- GEMM2 (fp16 2-term): both heads of this round ----
        #pragma unroll
        for (int which = 0; which < 2; which++) {
            const unsigned* AH = which ? p2h : a2h;
            const unsigned* AL = which ? p2l : a2l;
            const int s = which ? (wh ^ 1) : wh;
            unsigned b2_[4][4];
            #pragma unroll
            for (int g = 0; g < 4; g++) {
                int row = wh * 64 + g * 16 + b_r;
                unsigned off = (unsigned)(s * 4096 + row * 32 +
                                          ((b2c ^ ((row >> 2) & 1)) << 4));
                ldsm4(b2_[g], sb + OF_B2R + off);
            }
            #pragma unroll
            for (int j = 0; j < 8; j++) {
                const unsigned* BB = b2_[j >> 1] + (j & 1) * 2;
                mma_fp(d2[j], AH, BB);
                mma_fp(d2[j], AL, BB);
            }
        }
        __syncthreads();   // GEMM2 B2-slice + scratch reads done

        // refill B2 slice for next round
        if (r < 3) {
            const unsigned char* s1 = g_b2h + (r + 1) * 8192;
            #pragma unroll
            for (int it = 0; it < 2; it++) {
                int i = tid + it * NT;
                cp16(sb + OF_B2R + i * 16, s1 + i * 16);
            }
            asm volatile("cp.async.commit_group;" ::: "memory");
        }
    }

    // ---- epilogue: d2 + bias -> gmem ----
    {
        float* og = out + tb * 128;
        const int rl = wm * 16 + (lane >> 2);
        const int cb = wh * 64 + p * 2;
        #pragma unroll
        for (int j = 0; j < 8; j++) {
            int col = cb + j * 8;
            float b0 = sBp[col], b1 = sBp[col + 1];
            *(float2*)(og + rl * 128 + col) =
                make_float2(d2[j][0] + b0, d2[j][1] + b1);
            *(float2*)(og + (rl + 8) * 128 + col) =
                make_float2(d2[j][2] + b0, d2[j][3] + b1);
        }
    }
}

extern "C" void kernel_launch(void* const* d_in, const int* in_sizes, int n_in,
                              void* d_out, int out_size)
{
    const float *x = nullptr, *wq = nullptr, *bq = nullptr, *wp = nullptr, *bp = nullptr;
    long long xsz = 0;
    for (int i = 0; i < n_in; i++) {
        switch (in_sizes[i]) {
            case 49152: wq = (const float*)d_in[i]; break;
            case 384:   bq = (const float*)d_in[i]; break;
            case 16384: wp = (const float*)d_in[i]; break;
            case 128:   bp = (const float*)d_in[i]; break;
            default:    x  = (const float*)d_in[i]; xsz = in_sizes[i]; break;
        }
    }
    const int tokens = (int)(xsz / 128);

    prep_weights<<<32, 256>>>(wq, wp);

    cudaFuncSetAttribute(chan_attn_fp16,
                         cudaFuncAttributeMaxDynamicSharedMemorySize, SMEM_TOTAL);
    chan_attn_fp16<<<tokens / TOK, NT, SMEM_TOTAL>>>(x, bq, bp, (float*)d_out);
}

// round 17
// speedup vs baseline: 1.6728x; 1.0410x over previous
#include <cuda_runtime.h>
#include <cuda_bf16.h>
#include <cuda_fp16.h>

#define NT 256
#define TOK 64

// g_b1: w_qkv SINGLE-fp16 row-image: head-grouped rows n' = h*48+blk*16+ii
//       (-> col blk*128+h*16+ii), 256B rows, XOR-16B swizzle. 2 heads/round = 24KB.
// g_b2: w_proj SINGLE-fp16, per-ROUND slice layout:
//       offset = r*8192 + s*4096 + n*32 + ((c ^ ((n>>2)&1))<<4), head = 2r+s.
__device__ __align__(16) unsigned char g_b1h[98304];
__device__ __align__(16) unsigned char g_b2h[32768];

#define SWZ(r, b) ((unsigned)((r) * 256 + ((b) ^ (((r) & 7) << 4))))

// smem map (bytes) — 59392 total => 2 CTAs/SM
#define OF_BQ   0u        // 1536
#define OF_BP   1536u     // 512
#define OF_SCR  2048u     // 8192: A2-frag exchange [wid8][slot8][lane32]
#define OF_AH   10240u    // 16384: x image single fp16 (64 rows x 256B)
#define OF_B1   26624u    // 24576: current round B1 fp16 (2 heads, 96 rows)
#define OF_B2R  51200u    // 8192: current round B2 fp16 slice (2 slots x 4KB)
#define SMEM_TOTAL 59392

__device__ __forceinline__ unsigned smem_u32(const void* p) {
    unsigned a;
    asm("{ .reg .u64 t; cvta.to.shared.u64 t, %1; cvt.u32.u64 %0, t; }" : "=r"(a) : "l"(p));
    return a;
}
__device__ __forceinline__ unsigned pk2h(float a, float b) {     // fp16x2
    __half2 t = __floats2half2_rn(a, b);
    return *reinterpret_cast<unsigned*>(&t);
}
__device__ __forceinline__ float hfr(float v) {
    return __half2float(__float2half_rn(v));
}
__device__ __forceinline__ void ldsm4(unsigned* r, unsigned addr) {
    asm volatile("ldmatrix.sync.aligned.m8n8.x4.shared.b16 {%0,%1,%2,%3}, [%4];"
                 : "=r"(r[0]), "=r"(r[1]), "=r"(r[2]), "=r"(r[3]) : "r"(addr));
}
__device__ __forceinline__ void mma_fp(float* d, const unsigned* a, const unsigned* b) {
    asm volatile(
        "mma.sync.aligned.m16n8k16.row.col.f32.f16.f16.f32 "
        "{%0,%1,%2,%3}, {%4,%5,%6,%7}, {%8,%9}, {%0,%1,%2,%3};"
        : "+f"(d[0]), "+f"(d[1]), "+f"(d[2]), "+f"(d[3])
        : "r"(a[0]), "r"(a[1]), "r"(a[2]), "r"(a[3]), "r"(b[0]), "r"(b[1]));
}
__device__ __forceinline__ void cp16(unsigned dst, const void* src) {
    asm volatile("cp.async.cg.shared.global [%0], [%1], 16;" :: "r"(dst), "l"(src));
}
__device__ __forceinline__ unsigned hmul2u(unsigned a, unsigned b) {
    unsigned d;
    asm("mul.rn.f16x2 %0, %1, %2;" : "=r"(d) : "r"(a), "r"(b));
    return d;
}
__device__ __forceinline__ unsigned ex2h2(unsigned x) {          // 2 exps / 1 MUFU
    unsigned r;
    asm("ex2.approx.f16x2 %0, %1;" : "=r"(r) : "r"(x));
    return r;
}
__device__ __forceinline__ float rcpf(float x) {
    float r; asm("rcp.approx.f32 %0, %1;" : "=f"(r) : "f"(x)); return r;
}
// ---- packed fp32x2 (FFMA2 path — ptxas won't emit from C++) ----
__device__ __forceinline__ unsigned long long pack2f(float lo, float hi) {
    unsigned long long r;
    asm("mov.b64 %0, {%1, %2};" : "=l"(r) : "f"(lo), "f"(hi));
    return r;
}
__device__ __forceinline__ void unpack2f(unsigned long long v, float& lo, float& hi) {
    asm("mov.b64 {%0, %1}, %2;" : "=f"(lo), "=f"(hi) : "l"(v));
}
__device__ __forceinline__ unsigned long long ffma2(unsigned long long a,
                                                    unsigned long long b,
                                                    unsigned long long c) {
    unsigned long long d;
    asm("fma.rn.f32x2 %0, %1, %2, %3;" : "=l"(d) : "l"(a), "l"(b), "l"(c));
    return d;
}
__device__ __forceinline__ unsigned long long fadd2(unsigned long long a,
                                                    unsigned long long b) {
    unsigned long long d;
    asm("add.rn.f32x2 %0, %1, %2;" : "=l"(d) : "l"(a), "l"(b));
    return d;
}

// ---------------- prep: fp32 weights -> fp16 images ----------------
__global__ void prep_weights(const float* __restrict__ wq, const float* __restrict__ wp) {
    int i = blockIdx.x * blockDim.x + threadIdx.x;
    if (i < 6144) {                        // w_qkv: single fp16 row-image
        int n = i >> 4, kc = i & 15, k0 = kc * 8;
        int h = n / 48, rem = n % 48, blk = rem >> 4, ii = rem & 15;
        int col = blk * 128 + h * 16 + ii;
        float v[8];
        #pragma unroll
        for (int j = 0; j < 8; j++) v[j] = wq[(k0 + j) * 384 + col];
        unsigned off = SWZ(n, kc * 16);
        *(uint4*)(g_b1h + off) = make_uint4(pk2h(v[0], v[1]), pk2h(v[2], v[3]),
                                            pk2h(v[4], v[5]), pk2h(v[6], v[7]));
    } else if (i < 8192) {                 // w_proj: single fp16 per-round slices
        int j2 = i - 6144;
        int n = j2 >> 4, kc = j2 & 15, k0 = kc * 8;
        int hd = kc >> 1, c = kc & 1, r = hd >> 1, s = hd & 1;
        float v[8];
        #pragma unroll
        for (int j = 0; j < 8; j++) v[j] = wp[(k0 + j) * 128 + n];
        unsigned off = (unsigned)(r * 8192 + s * 4096 + n * 32 +
                                  ((c ^ ((n >> 2) & 1)) << 4));
        *(uint4*)(g_b2h + off) = make_uint4(pk2h(v[0], v[1]), pk2h(v[2], v[3]),
                                            pk2h(v[4], v[5]), pk2h(v[6], v[7]));
    }
}

// ---------------- main fused kernel: fp16 operands, f16x2 exp, f32x2 accum ----------------
__global__ void __launch_bounds__(NT, 2)
chan_attn_fp16(const float* __restrict__ x, const float* __restrict__ bq,
               const float* __restrict__ bp, float* __restrict__ out)
{
    extern __shared__ __align__(16) unsigned char smem[];
    const unsigned sb = smem_u32(smem);
    const int tid = threadIdx.x, wid = tid >> 5, lane = tid & 31;
    const int wm = wid >> 1, wh = wid & 1, p = lane & 3;
    const long long tb = (long long)blockIdx.x * TOK;

    float* sBq = (float*)(smem + OF_BQ);
    float* sBp = (float*)(smem + OF_BP);
    for (int i = tid; i < 384; i += NT) sBq[i] = bq[i];
    if (tid < 128) sBp[tid] = bp[tid];

    // prologue cp.async: B1 round0 (6 iters) + B2 slice round0 (2 iters)
    #pragma unroll
    for (int it = 0; it < 6; it++) {
        int i = tid + it * NT;
        cp16(sb + OF_B1 + i * 16, g_b1h + i * 16);
    }
    #pragma unroll
    for (int it = 0; it < 2; it++) {
        int i = tid + it * NT;
        cp16(sb + OF_B2R + i * 16, g_b2h + i * 16);
    }
    asm volatile("cp.async.commit_group;" ::: "memory");

    // build A image from x (single fp16, swizzled [m][k])
    {
        const float4* x4 = (const float4*)(x + tb * 128);
        #pragma unroll
        for (int it = 0; it < 8; it++) {
            int i = tid + it * NT;
            int m = i >> 5, c4 = i & 31;
            float4 v = x4[i];
            unsigned off = SWZ(m, c4 * 8);
            *(uint2*)(smem + OF_AH + off) = make_uint2(pk2h(v.x, v.y), pk2h(v.z, v.w));
        }
    }

    const int a_r = (lane & 7) + ((lane >> 3) & 1) * 8;
    const int a_bs = (lane >> 4) * 16;
    const int b_r = (lane & 7) + (lane >> 4) * 8;
    const int b_bs = ((lane >> 3) & 1) * 16;
    const int b2c = (lane >> 3) & 1;

    float d2[8][4] = {};   // GEMM2 accumulator: m16 x n64

    unsigned* scr = (unsigned*)(smem + OF_SCR);
    const int sbase = wid * 256 + lane;
    const int pbase = (wid ^ 1) * 256 + lane;

    #pragma unroll 1
    for (int r = 0; r < 4; r++) {
        asm volatile("cp.async.wait_group 0;" ::: "memory");
        __syncthreads();   // B1(r), B2 slice(r), (r==0: A image) resident

        // ---- GEMM1 (fp16 1-term): d1 = A[m16] @ B1[head 2r+wh]  (m16 x n48) ----
        float d1[6][4] = {};
        #pragma unroll
        for (int kc = 0; kc < 8; kc++) {
            const int kb = kc * 32;
            unsigned ah[4], bh[3][4];
            {
                unsigned off = SWZ(wm * 16 + a_r, kb + a_bs);
                ldsm4(ah, sb + OF_AH + off);
            }
            #pragma unroll
            for (int g = 0; g < 3; g++) {
                unsigned off = SWZ(wh * 48 + g * 16 + b_r, kb + b_bs);
                ldsm4(bh[g], sb + OF_B1 + off);
            }
            #pragma unroll
            for (int j = 0; j < 6; j++) {
                const unsigned* BH = bh[j >> 1] + (j & 1) * 2;
                mma_fp(d1[j], ah, BH);
            }
        }
        __syncthreads();   // all warps done reading B1

        // refill B1 for next round
        if (r < 3) {
            const unsigned char* s1 = g_b1h + (r + 1) * 24576;
            #pragma unroll
            for (int it = 0; it < 6; it++) {
                int i = tid + it * NT;
                cp16(sb + OF_B1 + i * 16, s1 + i * 16);
            }
            asm volatile("cp.async.commit_group;" ::: "memory");
        }

        // ---- softmax (head hh): f16x2 exp, packed-f32x2 accumulation ----
        const int hh = 2 * r + wh;
        unsigned a2h[4], a2l[4];
        {
            const float scl2 = 0.0883883476483184405f * 1.4426950408889634f;
            const int c0 = 2 * p, c2 = 8 + 2 * p;
            float qb0 = sBq[hh * 16 + c0], qb1 = sBq[hh * 16 + c0 + 1];
            float qb2 = sBq[hh * 16 + c2], qb3 = sBq[hh * 16 + c2 + 1];
            float kb0 = sBq[128 + hh * 16 + c0], kb1 = sBq[128 + hh * 16 + c0 + 1];
            float kb2 = sBq[128 + hh * 16 + c2], kb3 = sBq[128 + hh * 16 + c2 + 1];
            float vb0 = sBq[256 + hh * 16 + c0], vb1 = sBq[256 + hh * 16 + c0 + 1];
            float vb2 = sBq[256 + hh * 16 + c2], vb3 = sBq[256 + hh * 16 + c2 + 1];

            float o[2][4];
            #pragma unroll
            for (int rh = 0; rh < 2; rh++) {
                // own k/v values, packed fp16x2 BEFORE shuffles (halves SHFL count)
                unsigned kp0 = pk2h(d1[2][rh * 2 + 0] + kb0, d1[2][rh * 2 + 1] + kb1);
                unsigned kp1 = pk2h(d1[3][rh * 2 + 0] + kb2, d1[3][rh * 2 + 1] + kb3);
                unsigned vp0 = pk2h(d1[4][rh * 2 + 0] + vb0, d1[4][rh * 2 + 1] + vb1);
                unsigned vp1 = pk2h(d1[5][rh * 2 + 0] + vb2, d1[5][rh * 2 + 1] + vb3);
                unsigned kh[8], vhp[8];
                #pragma unroll
                for (int pp = 0; pp < 4; pp++) {
                    int sl = (lane & ~3) | pp;
                    kh[pp]      = __shfl_sync(0xffffffffu, kp0, sl);   // j = 2pp,2pp+1
                    kh[4 + pp]  = __shfl_sync(0xffffffffu, kp1, sl);   // j = 8+2pp,9+2pp
                    vhp[pp]     = __shfl_sync(0xffffffffu, vp0, sl);
                    vhp[4 + pp] = __shfl_sync(0xffffffffu, vp1, sl);
                }
                // v pairs -> packed f32x2 (once per rh, reused over 4 i)
                unsigned long long v2[8];
                #pragma unroll
                for (int jp = 0; jp < 8; jp++) {
                    __half2 vh2 = *reinterpret_cast<__half2*>(&vhp[jp]);
                    v2[jp] = pack2f(__low2float(vh2), __high2float(vh2));
                }
                float qv[4] = {qb0, qb1, qb2, qb3};
                #pragma unroll
                for (int i = 0; i < 4; i++) {
                    float ci = (d1[i >> 1][rh * 2 + (i & 1)] + qv[i]) * scl2;
                    unsigned ch = pk2h(ci, ci);
                    unsigned long long s2 = 0ULL, aa2 = 0ULL;
                    #pragma unroll
                    for (int jp = 0; jp < 8; jp++) {
                        unsigned e2u = ex2h2(hmul2u(ch, kh[jp]));
                        __half2 eh = *reinterpret_cast<__half2*>(&e2u);
                        unsigned long long e2 = pack2f(__low2float(eh), __high2float(eh));
                        s2 = fadd2(s2, e2);            // packed s even/odd
                        aa2 = ffma2(e2, v2[jp], aa2);  // packed a even/odd
                    }
                    float s_lo, s_hi, a_lo, a_hi;
                    unpack2f(s2, s_lo, s_hi);
                    unpack2f(aa2, a_lo, a_hi);
                    o[rh][i] = (a_lo + a_hi) * rcpf(s_lo + s_hi);
                }
            }
            // pack A2 fragments as fp16 hi/lo (exact split; consumed by fp16 GEMM2)
            float h00 = hfr(o[0][0]), h01 = hfr(o[0][1]);
            float h10 = hfr(o[1][0]), h11 = hfr(o[1][1]);
            float h02 = hfr(o[0][2]), h03 = hfr(o[0][3]);
            float h12 = hfr(o[1][2]), h13 = hfr(o[1][3]);
            a2h[0] = pk2h(h00, h01);  a2h[1] = pk2h(h10, h11);
            a2h[2] = pk2h(h02, h03);  a2h[3] = pk2h(h12, h13);
            a2l[0] = pk2h(o[0][0] - h00, o[0][1] - h01);
            a2l[1] = pk2h(o[1][0] - h10, o[1][1] - h11);
            a2l[2] = pk2h(o[0][2] - h02, o[0][3] - h03);
            a2l[3] = pk2h(o[1][2] - h12, o[1][3] - h13);
        }

        // ---- exchange A2 fragments with pair warp (other head of round) ----
        #pragma unroll
        for (int e = 0; e < 4; e++) {
            scr[sbase + e * 32] = a2h[e];
            scr[sbase + (4 + e) * 32] = a2l[e];
        }
        asm volatile("bar.sync %0, %1;" :: "r"(1 + wm), "r"(64) : "memory");
        unsigned p2h[4], p2l[4];
        #pragma unroll
        for (int e = 0; e < 4; e++) {
            p2h[e] = scr[pbase + e * 32];
            p2l[e] = scr[pbase + (4 + e) * 32];
        }

        // ---- GEMM2 (fp16 2-term): both heads of this round ----
        #pragma unroll
        for (int which = 0; which < 2; which++) {
            const unsigned* AH = which ? p2h : a2h;
            const unsigned* AL = which ? p2l : a2l;
            const int s = which ? (wh ^ 1) : wh;
            unsigned b2_[4][4];
            #pragma unroll
            for (int g = 0; g < 4; g++) {
                int row = wh * 64 + g * 16 + b_r;
                unsigned off = (unsigned)(s * 4096 + row * 32 +
                                          ((b2c ^ ((row >> 2) & 1)) << 4));
                ldsm4(b2_[g], sb + OF_B2R + off);
            }
            #pragma unroll
            for (int j = 0; j < 8; j++) {
                const unsigned* BB = b2_[j >> 1] + (j & 1) * 2;
                mma_fp(d2[j], AH, BB);
                mma_fp(d2[j], AL, BB);
            }
        }
        __syncthreads();   // GEMM2 B2-slice + scratch reads done

        // refill B2 slice for next round
        if (r < 3) {
            const unsigned char* s1 = g_b2h + (r + 1) * 8192;
            #pragma unroll
            for (int it = 0; it < 2; it++) {
                int i = tid + it * NT;
                cp16(sb + OF_B2R + i * 16, s1 + i * 16);
            }
            asm volatile("cp.async.commit_group;" ::: "memory");
        }
    }

    // ---- epilogue: d2 + bias -> gmem ----
    {
        float* og = out + tb * 128;
        const int rl = wm * 16 + (lane >> 2);
        const int cb = wh * 64 + p * 2;
        #pragma unroll
        for (int j = 0; j < 8; j++) {
            int col = cb + j * 8;
            float b0 = sBp[col], b1 = sBp[col + 1];
            *(float2*)(og + rl * 128 + col) =
                make_float2(d2[j][0] + b0, d2[j][1] + b1);
            *(float2*)(og + (rl + 8) * 128 + col) =
                make_float2(d2[j][2] + b0, d2[j][3] + b1);
        }
    }
}

extern "C" void kernel_launch(void* const* d_in, const int* in_sizes, int n_in,
                              void* d_out, int out_size)
{
    const float *x = nullptr, *wq = nullptr, *bq = nullptr, *wp = nullptr, *bp = nullptr;
    long long xsz = 0;
    for (int i = 0; i < n_in; i++) {
        switch (in_sizes[i]) {
            case 49152: wq = (const float*)d_in[i]; break;
            case 384:   bq = (const float*)d_in[i]; break;
            case 16384: wp = (const float*)d_in[i]; break;
            case 128:   bp = (const float*)d_in[i]; break;
            default:    x  = (const float*)d_in[i]; xsz = in_sizes[i]; break;
        }
    }
    const int tokens = (int)(xsz / 128);

    prep_weights<<<32, 256>>>(wq, wp);

    cudaFuncSetAttribute(chan_attn_fp16,
                         cudaFuncAttributeMaxDynamicSharedMemorySize, SMEM_TOTAL);
    chan_attn_fp16<<<tokens / TOK, NT, SMEM_TOTAL>>>(x, bq, bp, (float*)d_out);
}